// round 5
// baseline (speedup 1.0000x reference)
#include <cuda_runtime.h>
#include <math.h>

#define B_   2
#define S_   2048
#define C_   1024
#define H_   16
#define DH_  64
#define M_   (B_ * S_)       // 4096 rows

// ---- scratch (device globals; no allocation allowed) ----
__device__ float g_Q[M_ * C_];
__device__ float g_K[M_ * C_];
__device__ float g_V[M_ * C_];
__device__ float g_A[M_ * C_];           // attention output (pre out-proj)
__device__ float g_m1[B_ * H_ * S_];     // full-row max of scores (already /8)
__device__ float g_vs[B_ * H_ * DH_];    // sum over all keys of V per (b,h)

__device__ __forceinline__ unsigned f2tf(float x) {
    unsigned r;
    asm("cvt.rna.tf32.f32 %0, %1;" : "=r"(r) : "f"(x));
    return r;
}

// FMA-only exp (no MUFU). Valid for x in [-87, ~1.1]; rel err ~2.5e-6.
__device__ __forceinline__ float fexp(float x) {
    x = fmaxf(x, -87.0f);
    float z  = fmaf(x, 1.4426950408889634f, 12582912.0f);   // round-to-int trick
    int   n  = __float_as_int(z) - 0x4B400000;               // integer part
    float nf = z - 12582912.0f;
    float f  = fmaf(x, 1.4426950408889634f, -nf);            // frac in [-0.5, 0.5]
    float p  = 1.3333558146e-3f;
    p = fmaf(p, f, 9.6181291076e-3f);
    p = fmaf(p, f, 5.5504108664e-2f);
    p = fmaf(p, f, 2.4022650696e-1f);
    p = fmaf(p, f, 6.9314718056e-1f);
    p = fmaf(p, f, 1.0f);
    return p * __int_as_float((n + 127) << 23);
}

#define MMA_TF32(c, a, b)                                                     \
    asm volatile(                                                             \
        "mma.sync.aligned.m16n8k8.row.col.f32.tf32.tf32.f32 "                 \
        "{%0,%1,%2,%3},{%4,%5,%6,%7},{%8,%9},{%0,%1,%2,%3};"                  \
        : "+f"((c)[0]), "+f"((c)[1]), "+f"((c)[2]), "+f"((c)[3])              \
        : "r"((a)[0]), "r"((a)[1]), "r"((a)[2]), "r"((a)[3]),                 \
          "r"((b)[0]), "r"((b)[1]))

// ============================================================================
// tf32 tensor-core GEMM: C = A[M,K] @ B[K,N], 128x128x32 block tile,
// 8 warps (4x2), warp tile 32x64. B smem xor-swizzled (conflict-free loads).
// ============================================================================
__global__ __launch_bounds__(256) void tgemm(
    const float* __restrict__ A, const float* __restrict__ Bm,
    float* __restrict__ C, int M, int N, int K)
{
    __shared__ unsigned As[128][36];
    __shared__ unsigned Bs[32][128];

    const int tid = threadIdx.x;
    const int bm = blockIdx.y * 128;
    const int bn = blockIdx.x * 128;

    const int wid  = tid >> 5;
    const int lane = tid & 31;
    const int g    = lane >> 2;
    const int tig  = lane & 3;
    const int warpM = wid >> 1;
    const int warpN = wid & 1;
    const unsigned swz = tig << 3;

    const int a_m  = tid >> 1;
    const int a_k0 = (tid & 1) * 16;
    const int b_k  = tid >> 3;
    const int b_n0 = (tid & 7) * 16;
    const unsigned bswz = (b_k & 3) << 3;

    const float* Ap = A + (bm + a_m) * K + a_k0;
    const float* Bp = Bm + b_k * N + bn + b_n0;

    float c[2][8][4];
#pragma unroll
    for (int i = 0; i < 2; ++i)
#pragma unroll
        for (int j = 0; j < 8; ++j)
#pragma unroll
            for (int r = 0; r < 4; ++r) c[i][j][r] = 0.f;

    float4 av[4], bv[4];
#pragma unroll
    for (int j = 0; j < 4; ++j) {
        av[j] = *(const float4*)(Ap + j * 4);
        bv[j] = *(const float4*)(Bp + j * 4);
    }

    for (int kt = 0; kt < K; kt += 32) {
#pragma unroll
        for (int j = 0; j < 4; ++j) {
            uint4 ta, tb;
            ta.x = f2tf(av[j].x); ta.y = f2tf(av[j].y);
            ta.z = f2tf(av[j].z); ta.w = f2tf(av[j].w);
            tb.x = f2tf(bv[j].x); tb.y = f2tf(bv[j].y);
            tb.z = f2tf(bv[j].z); tb.w = f2tf(bv[j].w);
            *(uint4*)&As[a_m][a_k0 + j * 4] = ta;
            *(uint4*)&Bs[b_k][(b_n0 + j * 4) ^ bswz] = tb;
        }
        __syncthreads();

        if (kt + 32 < K) {
#pragma unroll
            for (int j = 0; j < 4; ++j) {
                av[j] = *(const float4*)(Ap + kt + 32 + j * 4);
                bv[j] = *(const float4*)(Bp + (kt + 32) * N + j * 4);
            }
        }

#pragma unroll
        for (int ks = 0; ks < 4; ++ks) {
            const int k0 = ks * 8;
            unsigned a[2][4];
#pragma unroll
            for (int m2 = 0; m2 < 2; ++m2) {
                const int mr = warpM * 32 + m2 * 16;
                a[m2][0] = As[mr + g][k0 + tig];
                a[m2][1] = As[mr + g + 8][k0 + tig];
                a[m2][2] = As[mr + g][k0 + tig + 4];
                a[m2][3] = As[mr + g + 8][k0 + tig + 4];
            }
#pragma unroll
            for (int j = 0; j < 8; ++j) {
                unsigned b[2];
                const unsigned nc = (unsigned)(warpN * 64 + j * 8 + g) ^ swz;
                b[0] = Bs[k0 + tig][nc];
                b[1] = Bs[k0 + tig + 4][nc];
                MMA_TF32(c[0][j], a[0], b);
                MMA_TF32(c[1][j], a[1], b);
            }
        }
        __syncthreads();
    }

#pragma unroll
    for (int m2 = 0; m2 < 2; ++m2) {
#pragma unroll
        for (int j = 0; j < 8; ++j) {
            const int row = bm + warpM * 32 + m2 * 16 + g;
            const int col = bn + warpN * 64 + j * 8 + 2 * tig;
            *(float2*)&C[row * N + col]       = make_float2(c[m2][j][0], c[m2][j][1]);
            *(float2*)&C[(row + 8) * N + col] = make_float2(c[m2][j][2], c[m2][j][3]);
        }
    }
}

// Fused QKV projections: blockIdx.z selects weight/output.
__global__ __launch_bounds__(256) void tgemm_qkv(
    const float* __restrict__ A,
    const float* __restrict__ W0, const float* __restrict__ W1,
    const float* __restrict__ W2,
    float* __restrict__ C0, float* __restrict__ C1, float* __restrict__ C2)
{
    const int z = blockIdx.z;
    const float* Bm = (z == 0) ? W0 : ((z == 1) ? W1 : W2);
    float* C = (z == 0) ? C0 : ((z == 1) ? C1 : C2);

    __shared__ unsigned As[128][36];
    __shared__ unsigned Bs[32][128];

    const int tid = threadIdx.x;
    const int bm = blockIdx.y * 128;
    const int bn = blockIdx.x * 128;
    const int N = C_, K = C_;

    const int wid  = tid >> 5;
    const int lane = tid & 31;
    const int g    = lane >> 2;
    const int tig  = lane & 3;
    const int warpM = wid >> 1;
    const int warpN = wid & 1;
    const unsigned swz = tig << 3;

    const int a_m  = tid >> 1;
    const int a_k0 = (tid & 1) * 16;
    const int b_k  = tid >> 3;
    const int b_n0 = (tid & 7) * 16;
    const unsigned bswz = (b_k & 3) << 3;

    const float* Ap = A + (bm + a_m) * K + a_k0;
    const float* Bp = Bm + b_k * N + bn + b_n0;

    float c[2][8][4];
#pragma unroll
    for (int i = 0; i < 2; ++i)
#pragma unroll
        for (int j = 0; j < 8; ++j)
#pragma unroll
            for (int r = 0; r < 4; ++r) c[i][j][r] = 0.f;

    float4 av[4], bv[4];
#pragma unroll
    for (int j = 0; j < 4; ++j) {
        av[j] = *(const float4*)(Ap + j * 4);
        bv[j] = *(const float4*)(Bp + j * 4);
    }

    for (int kt = 0; kt < K; kt += 32) {
#pragma unroll
        for (int j = 0; j < 4; ++j) {
            uint4 ta, tb;
            ta.x = f2tf(av[j].x); ta.y = f2tf(av[j].y);
            ta.z = f2tf(av[j].z); ta.w = f2tf(av[j].w);
            tb.x = f2tf(bv[j].x); tb.y = f2tf(bv[j].y);
            tb.z = f2tf(bv[j].z); tb.w = f2tf(bv[j].w);
            *(uint4*)&As[a_m][a_k0 + j * 4] = ta;
            *(uint4*)&Bs[b_k][(b_n0 + j * 4) ^ bswz] = tb;
        }
        __syncthreads();

        if (kt + 32 < K) {
#pragma unroll
            for (int j = 0; j < 4; ++j) {
                av[j] = *(const float4*)(Ap + kt + 32 + j * 4);
                bv[j] = *(const float4*)(Bp + (kt + 32) * N + j * 4);
            }
        }

#pragma unroll
        for (int ks = 0; ks < 4; ++ks) {
            const int k0 = ks * 8;
            unsigned a[2][4];
#pragma unroll
            for (int m2 = 0; m2 < 2; ++m2) {
                const int mr = warpM * 32 + m2 * 16;
                a[m2][0] = As[mr + g][k0 + tig];
                a[m2][1] = As[mr + g + 8][k0 + tig];
                a[m2][2] = As[mr + g][k0 + tig + 4];
                a[m2][3] = As[mr + g + 8][k0 + tig + 4];
            }
#pragma unroll
            for (int j = 0; j < 8; ++j) {
                unsigned b[2];
                const unsigned nc = (unsigned)(warpN * 64 + j * 8 + g) ^ swz;
                b[0] = Bs[k0 + tig][nc];
                b[1] = Bs[k0 + tig + 4][nc];
                MMA_TF32(c[0][j], a[0], b);
                MMA_TF32(c[1][j], a[1], b);
            }
        }
        __syncthreads();
    }

#pragma unroll
    for (int m2 = 0; m2 < 2; ++m2) {
#pragma unroll
        for (int j = 0; j < 8; ++j) {
            const int row = bm + warpM * 32 + m2 * 16 + g;
            const int col = bn + warpN * 64 + j * 8 + 2 * tig;
            *(float2*)&C[row * N + col]       = make_float2(c[m2][j][0], c[m2][j][1]);
            *(float2*)&C[(row + 8) * N + col] = make_float2(c[m2][j][2], c[m2][j][3]);
        }
    }
}

// ============================================================================
// tf32 score row-max: m1[bh][q] = max_k (q.k)/8.  (unchanged from R3)
// ============================================================================
__global__ __launch_bounds__(256, 2) void score_max_t(
    const float* __restrict__ Q, const float* __restrict__ K,
    float* __restrict__ m1)
{
    __shared__ unsigned Ks[2][64][68];
    __shared__ float buf[4][64];

    const int bh = blockIdx.y;
    const int b = bh >> 4, h = bh & 15;
    const int q0 = blockIdx.x * 64;
    const int tid = threadIdx.x;
    const int rowbase = (b * S_) * C_ + h * DH_;

    const int wid  = tid >> 5;
    const int lane = tid & 31;
    const int g    = lane >> 2;
    const int tig  = lane & 3;
    const int warpM = wid & 3;
    const int warpN = wid >> 2;

    const int ld_r = tid >> 2;
    const int ld_c = (tid & 3) * 4;

    {
        const float* qp = Q + rowbase + (q0 + ld_r) * C_ + ld_c;
#pragma unroll
        for (int j = 0; j < 4; ++j) {
            float4 v = *(const float4*)(qp + j * 16);
            Ks[0][ld_r][ld_c + j * 16 + 0] = f2tf(v.x);
            Ks[0][ld_r][ld_c + j * 16 + 1] = f2tf(v.y);
            Ks[0][ld_r][ld_c + j * 16 + 2] = f2tf(v.z);
            Ks[0][ld_r][ld_c + j * 16 + 3] = f2tf(v.w);
        }
    }
    __syncthreads();

    unsigned bq[4][8][2];
#pragma unroll
    for (int na = 0; na < 4; ++na) {
        const int nc = warpN * 32 + na * 8 + g;
#pragma unroll
        for (int ks = 0; ks < 8; ++ks) {
            bq[na][ks][0] = Ks[0][nc][ks * 8 + tig];
            bq[na][ks][1] = Ks[0][nc][ks * 8 + tig + 4];
        }
    }
    __syncthreads();

    float rmax[4][2];
#pragma unroll
    for (int na = 0; na < 4; ++na) { rmax[na][0] = -1e30f; rmax[na][1] = -1e30f; }

    float4 kv[4];
    {
        const float* kp = K + rowbase + ld_r * C_ + ld_c;
#pragma unroll
        for (int j = 0; j < 4; ++j) kv[j] = *(const float4*)(kp + j * 16);
    }

    for (int t = 0; t < S_ / 64; ++t) {
        const int cur = t & 1;
#pragma unroll
        for (int j = 0; j < 4; ++j) {
            Ks[cur][ld_r][ld_c + j * 16 + 0] = f2tf(kv[j].x);
            Ks[cur][ld_r][ld_c + j * 16 + 1] = f2tf(kv[j].y);
            Ks[cur][ld_r][ld_c + j * 16 + 2] = f2tf(kv[j].z);
            Ks[cur][ld_r][ld_c + j * 16 + 3] = f2tf(kv[j].w);
        }
        __syncthreads();

        if (t + 1 < S_ / 64) {
            const float* kp = K + rowbase + ((t + 1) * 64 + ld_r) * C_ + ld_c;
#pragma unroll
            for (int j = 0; j < 4; ++j) kv[j] = *(const float4*)(kp + j * 16);
        }

        float c[4][4];
#pragma unroll
        for (int na = 0; na < 4; ++na)
#pragma unroll
            for (int r = 0; r < 4; ++r) c[na][r] = 0.f;

        const int mr = warpM * 16;
#pragma unroll
        for (int ks = 0; ks < 8; ++ks) {
            const int k0 = ks * 8;
            unsigned a[4];
            a[0] = Ks[cur][mr + g][k0 + tig];
            a[1] = Ks[cur][mr + g + 8][k0 + tig];
            a[2] = Ks[cur][mr + g][k0 + tig + 4];
            a[3] = Ks[cur][mr + g + 8][k0 + tig + 4];
#pragma unroll
            for (int na = 0; na < 4; ++na)
                MMA_TF32(c[na], a, bq[na][ks]);
        }

#pragma unroll
        for (int na = 0; na < 4; ++na) {
            rmax[na][0] = fmaxf(rmax[na][0], fmaxf(c[na][0], c[na][2]));
            rmax[na][1] = fmaxf(rmax[na][1], fmaxf(c[na][1], c[na][3]));
        }
    }

#pragma unroll
    for (int off = 4; off <= 16; off <<= 1)
#pragma unroll
        for (int na = 0; na < 4; ++na) {
            rmax[na][0] = fmaxf(rmax[na][0], __shfl_xor_sync(0xffffffffu, rmax[na][0], off));
            rmax[na][1] = fmaxf(rmax[na][1], __shfl_xor_sync(0xffffffffu, rmax[na][1], off));
        }

    if (g == 0) {
#pragma unroll
        for (int na = 0; na < 4; ++na) {
            buf[warpM][warpN * 32 + na * 8 + tig * 2 + 0] = rmax[na][0];
            buf[warpM][warpN * 32 + na * 8 + tig * 2 + 1] = rmax[na][1];
        }
    }
    __syncthreads();
    if (tid < 64) {
        float m = fmaxf(fmaxf(buf[0][tid], buf[1][tid]),
                        fmaxf(buf[2][tid], buf[3][tid]));
        m1[bh * S_ + q0 + tid] = m * 0.125f;
    }
}

// ============================================================================
// V column sums per (b,h): vs[bh][d] = sum_k V[k][d]
// ============================================================================
__global__ __launch_bounds__(256) void vsum_k(
    const float* __restrict__ V, float* __restrict__ vs)
{
    __shared__ float red[4][64];
    const int bh = blockIdx.x;
    const int b = bh >> 4, h = bh & 15;
    const int tid = threadIdx.x;
    const int d = tid & 63, g = tid >> 6;
    const float* p = V + (b * S_) * C_ + h * DH_ + d;
    float s = 0.f;
    for (int k = g; k < S_; k += 4) s += p[k * C_];
    red[g][d] = s;
    __syncthreads();
    if (tid < 64)
        vs[bh * 64 + tid] = red[0][tid] + red[1][tid] + red[2][tid] + red[3][tid];
}

// ============================================================================
// Banded attention: 256 threads = 128 queries x 2 d-halves. FMA-only exp.
// out[q] = (sum_band (e^{t}-1) v + vsum) / (S + sum_band (e^{t}-1)),
// t = exp(s/8 - m1_q).
// ============================================================================
__global__ __launch_bounds__(256) void band_attn(
    const float* __restrict__ Q, const float* __restrict__ K,
    const float* __restrict__ V, const float* __restrict__ m1,
    const float* __restrict__ vs, float* __restrict__ O)
{
    __shared__ float Ks[64][64];
    __shared__ float Vs[64][64];

    const int bh = blockIdx.y;
    const int b = bh >> 4, h = bh & 15;
    const int q0 = blockIdx.x * 128;
    const int tid = threadIdx.x;
    const int qi = tid >> 1;        // 0..127
    const int ht = tid & 1;         // d-half
    const int q = q0 + qi;
    const int rowbase = (b * S_) * C_ + h * DH_;

    float qv[32];
    const float* qptr = Q + rowbase + q * C_ + ht * 32;
#pragma unroll
    for (int j = 0; j < 32; j += 4)
        *(float4*)&qv[j] = *(const float4*)(qptr + j);

    const float m1q = m1[bh * S_ + q];

    float acc[32];
#pragma unroll
    for (int j = 0; j < 32; ++j) acc[j] = 0.f;
    float Z = 0.f;

    const int klo  = (q0 >= 128) ? q0 - 128 : 0;               // 64-aligned
    const int kend = (q0 + 256 < S_) ? q0 + 256 : S_;          // last key: q0+127+128

    for (int kt = klo; kt < kend; kt += 64) {
        __syncthreads();
#pragma unroll
        for (int u = 0; u < 4; ++u) {
            int f = tid + 256 * u;      // 0..1023 float4 slots
            int kk = f >> 4;            // 0..63
            int d4 = (f & 15) * 4;
            int gg = rowbase + (kt + kk) * C_ + d4;
            *(float4*)&Ks[kk][d4] = *(const float4*)(K + gg);
            *(float4*)&Vs[kk][d4] = *(const float4*)(V + gg);
        }
        __syncthreads();

#pragma unroll 4
        for (int kk = 0; kk < 64; ++kk) {
            float s = 0.f;
#pragma unroll
            for (int j = 0; j < 32; j += 4) {
                float4 kvv = *(const float4*)&Ks[kk][ht * 32 + j];
                s = fmaf(qv[j + 0], kvv.x, s);
                s = fmaf(qv[j + 1], kvv.y, s);
                s = fmaf(qv[j + 2], kvv.z, s);
                s = fmaf(qv[j + 3], kvv.w, s);
            }
            s += __shfl_xor_sync(0xffffffffu, s, 1);
            float t = fexp(s * 0.125f - m1q);     // t in (0,~1]
            float w = fexp(t) - 1.0f;
            int d = kt + kk - q;
            if (d < -128 || d > 127) w = 0.f;     // outside band
            Z += w;
#pragma unroll
            for (int j = 0; j < 32; j += 4) {
                float4 vv = *(const float4*)&Vs[kk][ht * 32 + j];
                acc[j + 0] = fmaf(w, vv.x, acc[j + 0]);
                acc[j + 1] = fmaf(w, vv.y, acc[j + 1]);
                acc[j + 2] = fmaf(w, vv.z, acc[j + 2]);
                acc[j + 3] = fmaf(w, vv.w, acc[j + 3]);
            }
        }
    }

    const float inv = 1.0f / ((float)S_ + Z);
    const float* vsp = vs + bh * 64 + ht * 32;
    float* op = O + rowbase + q * C_ + ht * 32;
#pragma unroll
    for (int j = 0; j < 32; j += 4) {
        float4 vv = *(const float4*)(vsp + j);
        float4 o;
        o.x = (acc[j + 0] + vv.x) * inv;
        o.y = (acc[j + 1] + vv.y) * inv;
        o.z = (acc[j + 2] + vv.z) * inv;
        o.w = (acc[j + 3] + vv.w) * inv;
        *(float4*)(op + j) = o;
    }
}

// ============================================================================
extern "C" void kernel_launch(void* const* d_in, const int* in_sizes, int n_in,
                              void* d_out, int out_size)
{
    (void)in_sizes; (void)n_in; (void)out_size;
    const float* x  = (const float*)d_in[0];
    const float* Wq = (const float*)d_in[1];
    const float* Wk = (const float*)d_in[2];
    const float* Wv = (const float*)d_in[3];
    const float* Wo = (const float*)d_in[4];
    float* out = (float*)d_out;

    float *Qp, *Kp, *Vp, *Ap, *m1p, *vsp;
    cudaGetSymbolAddress((void**)&Qp,  g_Q);
    cudaGetSymbolAddress((void**)&Kp,  g_K);
    cudaGetSymbolAddress((void**)&Vp,  g_V);
    cudaGetSymbolAddress((void**)&Ap,  g_A);
    cudaGetSymbolAddress((void**)&m1p, g_m1);
    cudaGetSymbolAddress((void**)&vsp, g_vs);

    dim3 gq(C_ / 128, M_ / 128, 3);         // (8, 32, 3)
    tgemm_qkv<<<gq, 256>>>(x, Wq, Wk, Wv, Qp, Kp, Vp);

    score_max_t<<<dim3(S_ / 64, B_ * H_), 256>>>(Qp, Kp, m1p);
    vsum_k<<<B_ * H_, 256>>>(Vp, vsp);
    band_attn<<<dim3(S_ / 128, B_ * H_), 256>>>(Qp, Kp, Vp, m1p, vsp, Ap);

    dim3 gg(C_ / 128, M_ / 128);            // (8, 32)
    tgemm<<<gg, 256>>>(Ap, Wo, out, M_, C_, C_);
}

// round 6
// speedup vs baseline: 1.4656x; 1.4656x over previous
#include <cuda_runtime.h>
#include <math.h>

#define B_   2
#define S_   2048
#define C_   1024
#define H_   16
#define DH_  64
#define M_   (B_ * S_)       // 4096 rows

// ---- scratch (device globals; no allocation allowed) ----
__device__ float g_Q[M_ * C_];
__device__ float g_K[M_ * C_];
__device__ float g_V[M_ * C_];
__device__ float g_A[M_ * C_];           // attention output (pre out-proj)
__device__ float g_m1[B_ * H_ * S_];     // full-row max of scores (already /8)
__device__ float g_vs[B_ * H_ * DH_];    // sum over all keys of V per (b,h)

__device__ __forceinline__ unsigned f2tf(float x) {
    unsigned r;
    asm("cvt.rna.tf32.f32 %0, %1;" : "=r"(r) : "f"(x));
    return r;
}

#define MMA_TF32(c, a, b)                                                     \
    asm volatile(                                                             \
        "mma.sync.aligned.m16n8k8.row.col.f32.tf32.tf32.f32 "                 \
        "{%0,%1,%2,%3},{%4,%5,%6,%7},{%8,%9},{%0,%1,%2,%3};"                  \
        : "+f"((c)[0]), "+f"((c)[1]), "+f"((c)[2]), "+f"((c)[3])              \
        : "r"((a)[0]), "r"((a)[1]), "r"((a)[2]), "r"((a)[3]),                 \
          "r"((b)[0]), "r"((b)[1]))

// ============================================================================
// tf32 tensor-core GEMM: C = A[M,K] @ B[K,N], 128x128x32 block tile. (R4)
// ============================================================================
__global__ __launch_bounds__(256) void tgemm(
    const float* __restrict__ A, const float* __restrict__ Bm,
    float* __restrict__ C, int M, int N, int K)
{
    __shared__ unsigned As[128][36];
    __shared__ unsigned Bs[32][128];

    const int tid = threadIdx.x;
    const int bm = blockIdx.y * 128;
    const int bn = blockIdx.x * 128;

    const int wid  = tid >> 5;
    const int lane = tid & 31;
    const int g    = lane >> 2;
    const int tig  = lane & 3;
    const int warpM = wid >> 1;
    const int warpN = wid & 1;
    const unsigned swz = tig << 3;

    const int a_m  = tid >> 1;
    const int a_k0 = (tid & 1) * 16;
    const int b_k  = tid >> 3;
    const int b_n0 = (tid & 7) * 16;
    const unsigned bswz = (b_k & 3) << 3;

    const float* Ap = A + (bm + a_m) * K + a_k0;
    const float* Bp = Bm + b_k * N + bn + b_n0;

    float c[2][8][4];
#pragma unroll
    for (int i = 0; i < 2; ++i)
#pragma unroll
        for (int j = 0; j < 8; ++j)
#pragma unroll
            for (int r = 0; r < 4; ++r) c[i][j][r] = 0.f;

    float4 av[4], bv[4];
#pragma unroll
    for (int j = 0; j < 4; ++j) {
        av[j] = *(const float4*)(Ap + j * 4);
        bv[j] = *(const float4*)(Bp + j * 4);
    }

    for (int kt = 0; kt < K; kt += 32) {
#pragma unroll
        for (int j = 0; j < 4; ++j) {
            uint4 ta, tb;
            ta.x = f2tf(av[j].x); ta.y = f2tf(av[j].y);
            ta.z = f2tf(av[j].z); ta.w = f2tf(av[j].w);
            tb.x = f2tf(bv[j].x); tb.y = f2tf(bv[j].y);
            tb.z = f2tf(bv[j].z); tb.w = f2tf(bv[j].w);
            *(uint4*)&As[a_m][a_k0 + j * 4] = ta;
            *(uint4*)&Bs[b_k][(b_n0 + j * 4) ^ bswz] = tb;
        }
        __syncthreads();

        if (kt + 32 < K) {
#pragma unroll
            for (int j = 0; j < 4; ++j) {
                av[j] = *(const float4*)(Ap + kt + 32 + j * 4);
                bv[j] = *(const float4*)(Bp + (kt + 32) * N + j * 4);
            }
        }

#pragma unroll
        for (int ks = 0; ks < 4; ++ks) {
            const int k0 = ks * 8;
            unsigned a[2][4];
#pragma unroll
            for (int m2 = 0; m2 < 2; ++m2) {
                const int mr = warpM * 32 + m2 * 16;
                a[m2][0] = As[mr + g][k0 + tig];
                a[m2][1] = As[mr + g + 8][k0 + tig];
                a[m2][2] = As[mr + g][k0 + tig + 4];
                a[m2][3] = As[mr + g + 8][k0 + tig + 4];
            }
#pragma unroll
            for (int j = 0; j < 8; ++j) {
                unsigned b[2];
                const unsigned nc = (unsigned)(warpN * 64 + j * 8 + g) ^ swz;
                b[0] = Bs[k0 + tig][nc];
                b[1] = Bs[k0 + tig + 4][nc];
                MMA_TF32(c[0][j], a[0], b);
                MMA_TF32(c[1][j], a[1], b);
            }
        }
        __syncthreads();
    }

#pragma unroll
    for (int m2 = 0; m2 < 2; ++m2) {
#pragma unroll
        for (int j = 0; j < 8; ++j) {
            const int row = bm + warpM * 32 + m2 * 16 + g;
            const int col = bn + warpN * 64 + j * 8 + 2 * tig;
            *(float2*)&C[row * N + col]       = make_float2(c[m2][j][0], c[m2][j][1]);
            *(float2*)&C[(row + 8) * N + col] = make_float2(c[m2][j][2], c[m2][j][3]);
        }
    }
}

// Fused QKV projections: blockIdx.z selects weight/output. (R4)
__global__ __launch_bounds__(256) void tgemm_qkv(
    const float* __restrict__ A,
    const float* __restrict__ W0, const float* __restrict__ W1,
    const float* __restrict__ W2,
    float* __restrict__ C0, float* __restrict__ C1, float* __restrict__ C2)
{
    const int z = blockIdx.z;
    const float* Bm = (z == 0) ? W0 : ((z == 1) ? W1 : W2);
    float* C = (z == 0) ? C0 : ((z == 1) ? C1 : C2);

    __shared__ unsigned As[128][36];
    __shared__ unsigned Bs[32][128];

    const int tid = threadIdx.x;
    const int bm = blockIdx.y * 128;
    const int bn = blockIdx.x * 128;
    const int N = C_, K = C_;

    const int wid  = tid >> 5;
    const int lane = tid & 31;
    const int g    = lane >> 2;
    const int tig  = lane & 3;
    const int warpM = wid >> 1;
    const int warpN = wid & 1;
    const unsigned swz = tig << 3;

    const int a_m  = tid >> 1;
    const int a_k0 = (tid & 1) * 16;
    const int b_k  = tid >> 3;
    const int b_n0 = (tid & 7) * 16;
    const unsigned bswz = (b_k & 3) << 3;

    const float* Ap = A + (bm + a_m) * K + a_k0;
    const float* Bp = Bm + b_k * N + bn + b_n0;

    float c[2][8][4];
#pragma unroll
    for (int i = 0; i < 2; ++i)
#pragma unroll
        for (int j = 0; j < 8; ++j)
#pragma unroll
            for (int r = 0; r < 4; ++r) c[i][j][r] = 0.f;

    float4 av[4], bv[4];
#pragma unroll
    for (int j = 0; j < 4; ++j) {
        av[j] = *(const float4*)(Ap + j * 4);
        bv[j] = *(const float4*)(Bp + j * 4);
    }

    for (int kt = 0; kt < K; kt += 32) {
#pragma unroll
        for (int j = 0; j < 4; ++j) {
            uint4 ta, tb;
            ta.x = f2tf(av[j].x); ta.y = f2tf(av[j].y);
            ta.z = f2tf(av[j].z); ta.w = f2tf(av[j].w);
            tb.x = f2tf(bv[j].x); tb.y = f2tf(bv[j].y);
            tb.z = f2tf(bv[j].z); tb.w = f2tf(bv[j].w);
            *(uint4*)&As[a_m][a_k0 + j * 4] = ta;
            *(uint4*)&Bs[b_k][(b_n0 + j * 4) ^ bswz] = tb;
        }
        __syncthreads();

        if (kt + 32 < K) {
#pragma unroll
            for (int j = 0; j < 4; ++j) {
                av[j] = *(const float4*)(Ap + kt + 32 + j * 4);
                bv[j] = *(const float4*)(Bp + (kt + 32) * N + j * 4);
            }
        }

#pragma unroll
        for (int ks = 0; ks < 4; ++ks) {
            const int k0 = ks * 8;
            unsigned a[2][4];
#pragma unroll
            for (int m2 = 0; m2 < 2; ++m2) {
                const int mr = warpM * 32 + m2 * 16;
                a[m2][0] = As[mr + g][k0 + tig];
                a[m2][1] = As[mr + g + 8][k0 + tig];
                a[m2][2] = As[mr + g][k0 + tig + 4];
                a[m2][3] = As[mr + g + 8][k0 + tig + 4];
            }
#pragma unroll
            for (int j = 0; j < 8; ++j) {
                unsigned b[2];
                const unsigned nc = (unsigned)(warpN * 64 + j * 8 + g) ^ swz;
                b[0] = Bs[k0 + tig][nc];
                b[1] = Bs[k0 + tig + 4][nc];
                MMA_TF32(c[0][j], a[0], b);
                MMA_TF32(c[1][j], a[1], b);
            }
        }
        __syncthreads();
    }

#pragma unroll
    for (int m2 = 0; m2 < 2; ++m2) {
#pragma unroll
        for (int j = 0; j < 8; ++j) {
            const int row = bm + warpM * 32 + m2 * 16 + g;
            const int col = bn + warpN * 64 + j * 8 + 2 * tig;
            *(float2*)&C[row * N + col]       = make_float2(c[m2][j][0], c[m2][j][1]);
            *(float2*)&C[(row + 8) * N + col] = make_float2(c[m2][j][2], c[m2][j][3]);
        }
    }
}

// ============================================================================
// tf32 score row-max: m1[bh][q] = max_k (q.k)/8.  (unchanged from R3)
// ============================================================================
__global__ __launch_bounds__(256, 2) void score_max_t(
    const float* __restrict__ Q, const float* __restrict__ K,
    float* __restrict__ m1)
{
    __shared__ unsigned Ks[2][64][68];
    __shared__ float buf[4][64];

    const int bh = blockIdx.y;
    const int b = bh >> 4, h = bh & 15;
    const int q0 = blockIdx.x * 64;
    const int tid = threadIdx.x;
    const int rowbase = (b * S_) * C_ + h * DH_;

    const int wid  = tid >> 5;
    const int lane = tid & 31;
    const int g    = lane >> 2;
    const int tig  = lane & 3;
    const int warpM = wid & 3;
    const int warpN = wid >> 2;

    const int ld_r = tid >> 2;
    const int ld_c = (tid & 3) * 4;

    {
        const float* qp = Q + rowbase + (q0 + ld_r) * C_ + ld_c;
#pragma unroll
        for (int j = 0; j < 4; ++j) {
            float4 v = *(const float4*)(qp + j * 16);
            Ks[0][ld_r][ld_c + j * 16 + 0] = f2tf(v.x);
            Ks[0][ld_r][ld_c + j * 16 + 1] = f2tf(v.y);
            Ks[0][ld_r][ld_c + j * 16 + 2] = f2tf(v.z);
            Ks[0][ld_r][ld_c + j * 16 + 3] = f2tf(v.w);
        }
    }
    __syncthreads();

    unsigned bq[4][8][2];
#pragma unroll
    for (int na = 0; na < 4; ++na) {
        const int nc = warpN * 32 + na * 8 + g;
#pragma unroll
        for (int ks = 0; ks < 8; ++ks) {
            bq[na][ks][0] = Ks[0][nc][ks * 8 + tig];
            bq[na][ks][1] = Ks[0][nc][ks * 8 + tig + 4];
        }
    }
    __syncthreads();

    float rmax[4][2];
#pragma unroll
    for (int na = 0; na < 4; ++na) { rmax[na][0] = -1e30f; rmax[na][1] = -1e30f; }

    float4 kv[4];
    {
        const float* kp = K + rowbase + ld_r * C_ + ld_c;
#pragma unroll
        for (int j = 0; j < 4; ++j) kv[j] = *(const float4*)(kp + j * 16);
    }

    for (int t = 0; t < S_ / 64; ++t) {
        const int cur = t & 1;
#pragma unroll
        for (int j = 0; j < 4; ++j) {
            Ks[cur][ld_r][ld_c + j * 16 + 0] = f2tf(kv[j].x);
            Ks[cur][ld_r][ld_c + j * 16 + 1] = f2tf(kv[j].y);
            Ks[cur][ld_r][ld_c + j * 16 + 2] = f2tf(kv[j].z);
            Ks[cur][ld_r][ld_c + j * 16 + 3] = f2tf(kv[j].w);
        }
        __syncthreads();

        if (t + 1 < S_ / 64) {
            const float* kp = K + rowbase + ((t + 1) * 64 + ld_r) * C_ + ld_c;
#pragma unroll
            for (int j = 0; j < 4; ++j) kv[j] = *(const float4*)(kp + j * 16);
        }

        float c[4][4];
#pragma unroll
        for (int na = 0; na < 4; ++na)
#pragma unroll
            for (int r = 0; r < 4; ++r) c[na][r] = 0.f;

        const int mr = warpM * 16;
#pragma unroll
        for (int ks = 0; ks < 8; ++ks) {
            const int k0 = ks * 8;
            unsigned a[4];
            a[0] = Ks[cur][mr + g][k0 + tig];
            a[1] = Ks[cur][mr + g + 8][k0 + tig];
            a[2] = Ks[cur][mr + g][k0 + tig + 4];
            a[3] = Ks[cur][mr + g + 8][k0 + tig + 4];
#pragma unroll
            for (int na = 0; na < 4; ++na)
                MMA_TF32(c[na], a, bq[na][ks]);
        }

#pragma unroll
        for (int na = 0; na < 4; ++na) {
            rmax[na][0] = fmaxf(rmax[na][0], fmaxf(c[na][0], c[na][2]));
            rmax[na][1] = fmaxf(rmax[na][1], fmaxf(c[na][1], c[na][3]));
        }
    }

#pragma unroll
    for (int off = 4; off <= 16; off <<= 1)
#pragma unroll
        for (int na = 0; na < 4; ++na) {
            rmax[na][0] = fmaxf(rmax[na][0], __shfl_xor_sync(0xffffffffu, rmax[na][0], off));
            rmax[na][1] = fmaxf(rmax[na][1], __shfl_xor_sync(0xffffffffu, rmax[na][1], off));
        }

    if (g == 0) {
#pragma unroll
        for (int na = 0; na < 4; ++na) {
            buf[warpM][warpN * 32 + na * 8 + tig * 2 + 0] = rmax[na][0];
            buf[warpM][warpN * 32 + na * 8 + tig * 2 + 1] = rmax[na][1];
        }
    }
    __syncthreads();
    if (tid < 64) {
        float m = fmaxf(fmaxf(buf[0][tid], buf[1][tid]),
                        fmaxf(buf[2][tid], buf[3][tid]));
        m1[bh * S_ + q0 + tid] = m * 0.125f;
    }
}

// ============================================================================
// V column sums per (b,h): vs[bh][d] = sum_k V[k][d]
// ============================================================================
__global__ __launch_bounds__(256) void vsum_k(
    const float* __restrict__ V, float* __restrict__ vs)
{
    __shared__ float red[4][64];
    const int bh = blockIdx.x;
    const int b = bh >> 4, h = bh & 15;
    const int tid = threadIdx.x;
    const int d = tid & 63, g = tid >> 6;
    const float* p = V + (b * S_) * C_ + h * DH_ + d;
    float s = 0.f;
    for (int k = g; k < S_; k += 4) s += p[k * C_];
    red[g][d] = s;
    __syncthreads();
    if (tid < 64)
        vs[bh * 64 + tid] = red[0][tid] + red[1][tid] + red[2][tid] + red[3][tid];
}

// ============================================================================
// Tensor-core banded attention. Per block: 64 queries of one (b,h).
// For each 32-key tile in [q0-128, q0+192):
//   GEMM1: S^T[32k][64q] = K_tile @ Q^T   (tf32 MMA, all natural layouts)
//   exp/mask/Z in regs (weights tf32-rounded for numerator/denominator
//   consistency), store W^T[32k][64q] to smem
//   GEMM2: O[64q][64d] += W @ V_tile      (tf32 MMA)
// out = (O + vsum) / (S + Z).
// ============================================================================
__global__ __launch_bounds__(256) void band_attn_t(
    const float* __restrict__ Q, const float* __restrict__ K,
    const float* __restrict__ V, const float* __restrict__ m1,
    const float* __restrict__ vs, float* __restrict__ O)
{
    __shared__ unsigned Qs[64][68];   // [q][d]    17408 B
    __shared__ unsigned Ks[32][76];   // [key][d]   9728 B
    __shared__ unsigned Vs[32][76];   // [key][d]   9728 B
    __shared__ unsigned Ws[32][76];   // [key][q]   9728 B (W^T, tf32)
    __shared__ float zred[2][64];     //             512 B

    const int bh = blockIdx.y;
    const int b = bh >> 4, h = bh & 15;
    const int q0 = blockIdx.x * 64;
    const int tid = threadIdx.x;
    const int rowbase = (b * S_) * C_ + h * DH_;

    const int wid  = tid >> 5;
    const int lane = tid & 31;
    const int g    = lane >> 2;
    const int tig  = lane & 3;
    // GEMM1 layout: m = 32 keys (2 warp-rows of 16), n = 64 q (4 warp-cols of 16)
    const int wm1 = wid & 1;
    const int wn1 = wid >> 1;
    // GEMM2 layout: m = 64 q (4 warp-rows of 16), n = 64 d (2 warp-cols of 32)
    const int wm2 = wid >> 1;
    const int wn2 = wid & 1;

    // ---- load Q tile (64q x 64d), tf32 ----
    {
        const int r  = tid >> 2;
        const int c0 = (tid & 3) * 16;
        const float* qp = Q + rowbase + (q0 + r) * C_ + c0;
#pragma unroll
        for (int j = 0; j < 4; ++j) {
            float4 v = *(const float4*)(qp + j * 4);
            uint4 t;
            t.x = f2tf(v.x); t.y = f2tf(v.y); t.z = f2tf(v.z); t.w = f2tf(v.w);
            *(uint4*)&Qs[r][c0 + j * 4] = t;
        }
    }
    __syncthreads();

    // hoist Q B-fragments (reused for every key tile)
    unsigned bq[2][8][2];
#pragma unroll
    for (int na = 0; na < 2; ++na) {
        const int nc = wn1 * 16 + na * 8 + g;
#pragma unroll
        for (int ks = 0; ks < 8; ++ks) {
            bq[na][ks][0] = Qs[nc][ks * 8 + tig];
            bq[na][ks][1] = Qs[nc][ks * 8 + tig + 4];
        }
    }
    // per-column m1 (GEMM1 cols = queries)
    float m1c[2][2];
#pragma unroll
    for (int na = 0; na < 2; ++na) {
        const int qc = q0 + wn1 * 16 + na * 8 + 2 * tig;
        m1c[na][0] = m1[bh * S_ + qc];
        m1c[na][1] = m1[bh * S_ + qc + 1];
    }

    float o[4][4];
#pragma unroll
    for (int na = 0; na < 4; ++na)
#pragma unroll
        for (int r = 0; r < 4; ++r) o[na][r] = 0.f;
    float zp[2][2] = {{0.f, 0.f}, {0.f, 0.f}};

    const int klo  = (q0 >= 128) ? q0 - 128 : 0;
    const int kend = (q0 + 192 < S_) ? q0 + 192 : S_;

    for (int kt = klo; kt < kend; kt += 32) {
        __syncthreads();   // KV/Ws safe to overwrite (prev GEMM2 done)
        // ---- load K,V tiles (32k x 64d), tf32 ----
        {
            const int r  = tid >> 3;
            const int c0 = (tid & 7) * 8;
            const float* kp = K + rowbase + (kt + r) * C_ + c0;
            const float* vp = V + rowbase + (kt + r) * C_ + c0;
#pragma unroll
            for (int j = 0; j < 2; ++j) {
                float4 a = *(const float4*)(kp + j * 4);
                float4 c = *(const float4*)(vp + j * 4);
                uint4 ta, tc;
                ta.x = f2tf(a.x); ta.y = f2tf(a.y); ta.z = f2tf(a.z); ta.w = f2tf(a.w);
                tc.x = f2tf(c.x); tc.y = f2tf(c.y); tc.z = f2tf(c.z); tc.w = f2tf(c.w);
                *(uint4*)&Ks[r][c0 + j * 4] = ta;
                *(uint4*)&Vs[r][c0 + j * 4] = tc;
            }
        }
        __syncthreads();

        // ---- GEMM1: S^T[key][q] ----
        float s[2][4];
#pragma unroll
        for (int na = 0; na < 2; ++na)
#pragma unroll
            for (int r = 0; r < 4; ++r) s[na][r] = 0.f;

        const int mr1 = wm1 * 16;
#pragma unroll
        for (int ks = 0; ks < 8; ++ks) {
            const int k0 = ks * 8;
            unsigned a[4];
            a[0] = Ks[mr1 + g][k0 + tig];
            a[1] = Ks[mr1 + g + 8][k0 + tig];
            a[2] = Ks[mr1 + g][k0 + tig + 4];
            a[3] = Ks[mr1 + g + 8][k0 + tig + 4];
            MMA_TF32(s[0], a, bq[0][ks]);
            MMA_TF32(s[1], a, bq[1][ks]);
        }

        // ---- exp / band mask / Z, store W^T (tf32) ----
#pragma unroll
        for (int na = 0; na < 2; ++na) {
            const int colq = wn1 * 16 + na * 8 + 2 * tig;  // query within tile
#pragma unroll
            for (int r2 = 0; r2 < 2; ++r2) {
                const int keyrow = wm1 * 16 + g + r2 * 8;
                const int key = kt + keyrow;
#pragma unroll
                for (int j = 0; j < 2; ++j) {
                    const float sv = s[na][r2 * 2 + j];
                    const int d = key - (q0 + colq + j);
                    float t = __expf(sv * 0.125f - m1c[na][j]);
                    float w = __expf(t) - 1.0f;
                    if (d < -128 || d > 127) w = 0.f;
                    const unsigned wt = f2tf(w);
                    zp[na][j] += __uint_as_float(wt);
                    Ws[keyrow][colq + j] = wt;
                }
            }
        }
        __syncthreads();   // W^T visible

        // ---- GEMM2: O += W @ V ----
        const int mr2 = wm2 * 16;
#pragma unroll
        for (int ks = 0; ks < 4; ++ks) {
            const int k0 = ks * 8;
            unsigned a[4];
            a[0] = Ws[k0 + tig][mr2 + g];
            a[1] = Ws[k0 + tig][mr2 + g + 8];
            a[2] = Ws[k0 + tig + 4][mr2 + g];
            a[3] = Ws[k0 + tig + 4][mr2 + g + 8];
#pragma unroll
            for (int na = 0; na < 4; ++na) {
                unsigned bb[2];
                const int nc = wn2 * 32 + na * 8 + g;
                bb[0] = Vs[k0 + tig][nc];
                bb[1] = Vs[k0 + tig + 4][nc];
                MMA_TF32(o[na], a, bb);
            }
        }
    }

    // ---- Z reduction: sum over g lanes, then over the 2 key-warp-rows ----
#pragma unroll
    for (int off = 4; off <= 16; off <<= 1)
#pragma unroll
        for (int na = 0; na < 2; ++na) {
            zp[na][0] += __shfl_xor_sync(0xffffffffu, zp[na][0], off);
            zp[na][1] += __shfl_xor_sync(0xffffffffu, zp[na][1], off);
        }
    if (g == 0) {
#pragma unroll
        for (int na = 0; na < 2; ++na) {
            zred[wm1][wn1 * 16 + na * 8 + 2 * tig + 0] = zp[na][0];
            zred[wm1][wn1 * 16 + na * 8 + 2 * tig + 1] = zp[na][1];
        }
    }
    __syncthreads();

    // ---- epilogue: out = (O + vsum) / (S + Z) ----
    const float* vsp = vs + bh * 64;
#pragma unroll
    for (int r2 = 0; r2 < 2; ++r2) {
        const int row = wm2 * 16 + g + r2 * 8;           // query within tile
        const float inv = 1.0f / ((float)S_ + zred[0][row] + zred[1][row]);
        float* op = O + rowbase + (q0 + row) * C_;
#pragma unroll
        for (int na = 0; na < 4; ++na) {
            const int col = wn2 * 32 + na * 8 + 2 * tig;
            float2 ov;
            ov.x = (o[na][r2 * 2 + 0] + vsp[col])     * inv;
            ov.y = (o[na][r2 * 2 + 1] + vsp[col + 1]) * inv;
            *(float2*)(op + col) = ov;
        }
    }
}

// ============================================================================
extern "C" void kernel_launch(void* const* d_in, const int* in_sizes, int n_in,
                              void* d_out, int out_size)
{
    (void)in_sizes; (void)n_in; (void)out_size;
    const float* x  = (const float*)d_in[0];
    const float* Wq = (const float*)d_in[1];
    const float* Wk = (const float*)d_in[2];
    const float* Wv = (const float*)d_in[3];
    const float* Wo = (const float*)d_in[4];
    float* out = (float*)d_out;

    float *Qp, *Kp, *Vp, *Ap, *m1p, *vsp;
    cudaGetSymbolAddress((void**)&Qp,  g_Q);
    cudaGetSymbolAddress((void**)&Kp,  g_K);
    cudaGetSymbolAddress((void**)&Vp,  g_V);
    cudaGetSymbolAddress((void**)&Ap,  g_A);
    cudaGetSymbolAddress((void**)&m1p, g_m1);
    cudaGetSymbolAddress((void**)&vsp, g_vs);

    dim3 gq(C_ / 128, M_ / 128, 3);         // (8, 32, 3)
    tgemm_qkv<<<gq, 256>>>(x, Wq, Wk, Wv, Qp, Kp, Vp);

    score_max_t<<<dim3(S_ / 64, B_ * H_), 256>>>(Qp, Kp, m1p);
    vsum_k<<<B_ * H_, 256>>>(Vp, vsp);
    band_attn_t<<<dim3(S_ / 64, B_ * H_), 256>>>(Qp, Kp, Vp, m1p, vsp, Ap);

    dim3 gg(C_ / 128, M_ / 128);            // (8, 32)
    tgemm<<<gg, 256>>>(Ap, Wo, out, M_, C_, C_);
}

// round 7
// speedup vs baseline: 1.6622x; 1.1341x over previous
#include <cuda_runtime.h>
#include <math.h>

#define B_   2
#define S_   2048
#define C_   1024
#define H_   16
#define DH_  64
#define M_   (B_ * S_)       // 4096 rows

// ---- scratch (device globals; no allocation allowed) ----
__device__ float g_Q[M_ * C_];
__device__ float g_K[M_ * C_];
__device__ float g_V[M_ * C_];
__device__ float g_A[M_ * C_];           // attention output (pre out-proj)
__device__ float g_m1[B_ * H_ * S_];     // full-row max of scores (already /8)
__device__ float g_vs[B_ * H_ * DH_];    // sum over all keys of V per (b,h)

__device__ __forceinline__ unsigned f2tf(float x) {
    unsigned r;
    asm("cvt.rna.tf32.f32 %0, %1;" : "=r"(r) : "f"(x));
    return r;
}

#define MMA_TF32(c, a, b)                                                     \
    asm volatile(                                                             \
        "mma.sync.aligned.m16n8k8.row.col.f32.tf32.tf32.f32 "                 \
        "{%0,%1,%2,%3},{%4,%5,%6,%7},{%8,%9},{%0,%1,%2,%3};"                  \
        : "+f"((c)[0]), "+f"((c)[1]), "+f"((c)[2]), "+f"((c)[3])              \
        : "r"((a)[0]), "r"((a)[1]), "r"((a)[2]), "r"((a)[3]),                 \
          "r"((b)[0]), "r"((b)[1]))

// dynamic smem: As[2][128][36] + Bs[2][32][128] (tf32 words)
#define GEMM_SMEM_WORDS (2 * 128 * 36 + 2 * 32 * 128)
#define GEMM_SMEM_BYTES (GEMM_SMEM_WORDS * 4)

// ============================================================================
// Double-buffered tf32 GEMM body: C = A[M,K] @ B[K,N], 128x128x32 tile,
// 8 warps (4x2), warp tile 32x64, one __syncthreads per K-tile.
// ============================================================================
__device__ __forceinline__ void gemm_body(
    const float* __restrict__ A, const float* __restrict__ Bm,
    float* __restrict__ C, int N, int K)
{
    extern __shared__ unsigned smbuf[];
    unsigned (*As)[128][36] = reinterpret_cast<unsigned(*)[128][36]>(smbuf);
    unsigned (*Bs)[32][128] =
        reinterpret_cast<unsigned(*)[32][128]>(smbuf + 2 * 128 * 36);

    const int tid = threadIdx.x;
    const int bm = blockIdx.y * 128;
    const int bn = blockIdx.x * 128;

    const int wid  = tid >> 5;
    const int lane = tid & 31;
    const int g    = lane >> 2;
    const int tig  = lane & 3;
    const int warpM = wid >> 1;
    const int warpN = wid & 1;
    const unsigned swz = tig << 3;

    const int a_m  = tid >> 1;
    const int a_k0 = (tid & 1) * 16;
    const int b_k  = tid >> 3;
    const int b_n0 = (tid & 7) * 16;
    const unsigned bswz = (b_k & 3) << 3;

    const float* Ap = A + (bm + a_m) * K + a_k0;
    const float* Bp = Bm + b_k * N + bn + b_n0;

    float c[2][8][4];
#pragma unroll
    for (int i = 0; i < 2; ++i)
#pragma unroll
        for (int j = 0; j < 8; ++j)
#pragma unroll
            for (int r = 0; r < 4; ++r) c[i][j][r] = 0.f;

    float4 av[4], bv[4];
#pragma unroll
    for (int j = 0; j < 4; ++j) {
        av[j] = *(const float4*)(Ap + j * 4);
        bv[j] = *(const float4*)(Bp + j * 4);
    }
#pragma unroll
    for (int j = 0; j < 4; ++j) {
        uint4 ta, tb;
        ta.x = f2tf(av[j].x); ta.y = f2tf(av[j].y);
        ta.z = f2tf(av[j].z); ta.w = f2tf(av[j].w);
        tb.x = f2tf(bv[j].x); tb.y = f2tf(bv[j].y);
        tb.z = f2tf(bv[j].z); tb.w = f2tf(bv[j].w);
        *(uint4*)&As[0][a_m][a_k0 + j * 4] = ta;
        *(uint4*)&Bs[0][b_k][(b_n0 + j * 4) ^ bswz] = tb;
    }
    __syncthreads();

    const int nt = K >> 5;
    for (int t = 0; t < nt; ++t) {
        const int cur = t & 1;
        if (t + 1 < nt) {
#pragma unroll
            for (int j = 0; j < 4; ++j) {
                av[j] = *(const float4*)(Ap + (t + 1) * 32 + j * 4);
                bv[j] = *(const float4*)(Bp + (t + 1) * 32 * N + j * 4);
            }
        }

#pragma unroll
        for (int ks = 0; ks < 4; ++ks) {
            const int k0 = ks * 8;
            unsigned a[2][4];
#pragma unroll
            for (int m2 = 0; m2 < 2; ++m2) {
                const int mr = warpM * 32 + m2 * 16;
                a[m2][0] = As[cur][mr + g][k0 + tig];
                a[m2][1] = As[cur][mr + g + 8][k0 + tig];
                a[m2][2] = As[cur][mr + g][k0 + tig + 4];
                a[m2][3] = As[cur][mr + g + 8][k0 + tig + 4];
            }
#pragma unroll
            for (int j = 0; j < 8; ++j) {
                unsigned b[2];
                const unsigned nc = (unsigned)(warpN * 64 + j * 8 + g) ^ swz;
                b[0] = Bs[cur][k0 + tig][nc];
                b[1] = Bs[cur][k0 + tig + 4][nc];
                MMA_TF32(c[0][j], a[0], b);
                MMA_TF32(c[1][j], a[1], b);
            }
        }

        if (t + 1 < nt) {
            const int nxt = cur ^ 1;
#pragma unroll
            for (int j = 0; j < 4; ++j) {
                uint4 ta, tb;
                ta.x = f2tf(av[j].x); ta.y = f2tf(av[j].y);
                ta.z = f2tf(av[j].z); ta.w = f2tf(av[j].w);
                tb.x = f2tf(bv[j].x); tb.y = f2tf(bv[j].y);
                tb.z = f2tf(bv[j].z); tb.w = f2tf(bv[j].w);
                *(uint4*)&As[nxt][a_m][a_k0 + j * 4] = ta;
                *(uint4*)&Bs[nxt][b_k][(b_n0 + j * 4) ^ bswz] = tb;
            }
        }
        __syncthreads();
    }

#pragma unroll
    for (int m2 = 0; m2 < 2; ++m2) {
#pragma unroll
        for (int j = 0; j < 8; ++j) {
            const int row = bm + warpM * 32 + m2 * 16 + g;
            const int col = bn + warpN * 64 + j * 8 + 2 * tig;
            *(float2*)&C[row * N + col]       = make_float2(c[m2][j][0], c[m2][j][1]);
            *(float2*)&C[(row + 8) * N + col] = make_float2(c[m2][j][2], c[m2][j][3]);
        }
    }
}

__global__ __launch_bounds__(256, 2) void tgemm_db(
    const float* __restrict__ A, const float* __restrict__ Bm,
    float* __restrict__ C, int N, int K)
{
    gemm_body(A, Bm, C, N, K);
}

__global__ __launch_bounds__(256, 2) void tgemm_qkv_db(
    const float* __restrict__ A,
    const float* __restrict__ W0, const float* __restrict__ W1,
    const float* __restrict__ W2,
    float* __restrict__ C0, float* __restrict__ C1, float* __restrict__ C2)
{
    const int z = blockIdx.z;
    const float* Bm = (z == 0) ? W0 : ((z == 1) ? W1 : W2);
    float* C = (z == 0) ? C0 : ((z == 1) ? C1 : C2);
    gemm_body(A, Bm, C, C_, C_);
}

// ============================================================================
// tf32 score row-max: m1[bh][q] = max_k (q.k)/8.  (unchanged from R3)
// ============================================================================
__global__ __launch_bounds__(256, 2) void score_max_t(
    const float* __restrict__ Q, const float* __restrict__ K,
    float* __restrict__ m1)
{
    __shared__ unsigned Ks[2][64][68];
    __shared__ float buf[4][64];

    const int bh = blockIdx.y;
    const int b = bh >> 4, h = bh & 15;
    const int q0 = blockIdx.x * 64;
    const int tid = threadIdx.x;
    const int rowbase = (b * S_) * C_ + h * DH_;

    const int wid  = tid >> 5;
    const int lane = tid & 31;
    const int g    = lane >> 2;
    const int tig  = lane & 3;
    const int warpM = wid & 3;
    const int warpN = wid >> 2;

    const int ld_r = tid >> 2;
    const int ld_c = (tid & 3) * 4;

    {
        const float* qp = Q + rowbase + (q0 + ld_r) * C_ + ld_c;
#pragma unroll
        for (int j = 0; j < 4; ++j) {
            float4 v = *(const float4*)(qp + j * 16);
            Ks[0][ld_r][ld_c + j * 16 + 0] = f2tf(v.x);
            Ks[0][ld_r][ld_c + j * 16 + 1] = f2tf(v.y);
            Ks[0][ld_r][ld_c + j * 16 + 2] = f2tf(v.z);
            Ks[0][ld_r][ld_c + j * 16 + 3] = f2tf(v.w);
        }
    }
    __syncthreads();

    unsigned bq[4][8][2];
#pragma unroll
    for (int na = 0; na < 4; ++na) {
        const int nc = warpN * 32 + na * 8 + g;
#pragma unroll
        for (int ks = 0; ks < 8; ++ks) {
            bq[na][ks][0] = Ks[0][nc][ks * 8 + tig];
            bq[na][ks][1] = Ks[0][nc][ks * 8 + tig + 4];
        }
    }
    __syncthreads();

    float rmax[4][2];
#pragma unroll
    for (int na = 0; na < 4; ++na) { rmax[na][0] = -1e30f; rmax[na][1] = -1e30f; }

    float4 kv[4];
    {
        const float* kp = K + rowbase + ld_r * C_ + ld_c;
#pragma unroll
        for (int j = 0; j < 4; ++j) kv[j] = *(const float4*)(kp + j * 16);
    }

    for (int t = 0; t < S_ / 64; ++t) {
        const int cur = t & 1;
#pragma unroll
        for (int j = 0; j < 4; ++j) {
            Ks[cur][ld_r][ld_c + j * 16 + 0] = f2tf(kv[j].x);
            Ks[cur][ld_r][ld_c + j * 16 + 1] = f2tf(kv[j].y);
            Ks[cur][ld_r][ld_c + j * 16 + 2] = f2tf(kv[j].z);
            Ks[cur][ld_r][ld_c + j * 16 + 3] = f2tf(kv[j].w);
        }
        __syncthreads();

        if (t + 1 < S_ / 64) {
            const float* kp = K + rowbase + ((t + 1) * 64 + ld_r) * C_ + ld_c;
#pragma unroll
            for (int j = 0; j < 4; ++j) kv[j] = *(const float4*)(kp + j * 16);
        }

        float c[4][4];
#pragma unroll
        for (int na = 0; na < 4; ++na)
#pragma unroll
            for (int r = 0; r < 4; ++r) c[na][r] = 0.f;

        const int mr = warpM * 16;
#pragma unroll
        for (int ks = 0; ks < 8; ++ks) {
            const int k0 = ks * 8;
            unsigned a[4];
            a[0] = Ks[cur][mr + g][k0 + tig];
            a[1] = Ks[cur][mr + g + 8][k0 + tig];
            a[2] = Ks[cur][mr + g][k0 + tig + 4];
            a[3] = Ks[cur][mr + g + 8][k0 + tig + 4];
#pragma unroll
            for (int na = 0; na < 4; ++na)
                MMA_TF32(c[na], a, bq[na][ks]);
        }

#pragma unroll
        for (int na = 0; na < 4; ++na) {
            rmax[na][0] = fmaxf(rmax[na][0], fmaxf(c[na][0], c[na][2]));
            rmax[na][1] = fmaxf(rmax[na][1], fmaxf(c[na][1], c[na][3]));
        }
    }

#pragma unroll
    for (int off = 4; off <= 16; off <<= 1)
#pragma unroll
        for (int na = 0; na < 4; ++na) {
            rmax[na][0] = fmaxf(rmax[na][0], __shfl_xor_sync(0xffffffffu, rmax[na][0], off));
            rmax[na][1] = fmaxf(rmax[na][1], __shfl_xor_sync(0xffffffffu, rmax[na][1], off));
        }

    if (g == 0) {
#pragma unroll
        for (int na = 0; na < 4; ++na) {
            buf[warpM][warpN * 32 + na * 8 + tig * 2 + 0] = rmax[na][0];
            buf[warpM][warpN * 32 + na * 8 + tig * 2 + 1] = rmax[na][1];
        }
    }
    __syncthreads();
    if (tid < 64) {
        float m = fmaxf(fmaxf(buf[0][tid], buf[1][tid]),
                        fmaxf(buf[2][tid], buf[3][tid]));
        m1[bh * S_ + q0 + tid] = m * 0.125f;
    }
}

// ============================================================================
// V column sums per (b,h): vs[bh][d] = sum_k V[k][d]
// ============================================================================
__global__ __launch_bounds__(256) void vsum_k(
    const float* __restrict__ V, float* __restrict__ vs)
{
    __shared__ float red[4][64];
    const int bh = blockIdx.x;
    const int b = bh >> 4, h = bh & 15;
    const int tid = threadIdx.x;
    const int d = tid & 63, g = tid >> 6;
    const float* p = V + (b * S_) * C_ + h * DH_ + d;
    float s = 0.f;
    for (int k = g; k < S_; k += 4) s += p[k * C_];
    red[g][d] = s;
    __syncthreads();
    if (tid < 64)
        vs[bh * 64 + tid] = red[0][tid] + red[1][tid] + red[2][tid] + red[3][tid];
}

// ============================================================================
// Tensor-core banded attention (unchanged from R6 winner).
// ============================================================================
__global__ __launch_bounds__(256) void band_attn_t(
    const float* __restrict__ Q, const float* __restrict__ K,
    const float* __restrict__ V, const float* __restrict__ m1,
    const float* __restrict__ vs, float* __restrict__ O)
{
    __shared__ unsigned Qs[64][68];
    __shared__ unsigned Ks[32][76];
    __shared__ unsigned Vs[32][76];
    __shared__ unsigned Ws[32][76];
    __shared__ float zred[2][64];

    const int bh = blockIdx.y;
    const int b = bh >> 4, h = bh & 15;
    const int q0 = blockIdx.x * 64;
    const int tid = threadIdx.x;
    const int rowbase = (b * S_) * C_ + h * DH_;

    const int wid  = tid >> 5;
    const int lane = tid & 31;
    const int g    = lane >> 2;
    const int tig  = lane & 3;
    const int wm1 = wid & 1;
    const int wn1 = wid >> 1;
    const int wm2 = wid >> 1;
    const int wn2 = wid & 1;

    {
        const int r  = tid >> 2;
        const int c0 = (tid & 3) * 16;
        const float* qp = Q + rowbase + (q0 + r) * C_ + c0;
#pragma unroll
        for (int j = 0; j < 4; ++j) {
            float4 v = *(const float4*)(qp + j * 4);
            uint4 t;
            t.x = f2tf(v.x); t.y = f2tf(v.y); t.z = f2tf(v.z); t.w = f2tf(v.w);
            *(uint4*)&Qs[r][c0 + j * 4] = t;
        }
    }
    __syncthreads();

    unsigned bq[2][8][2];
#pragma unroll
    for (int na = 0; na < 2; ++na) {
        const int nc = wn1 * 16 + na * 8 + g;
#pragma unroll
        for (int ks = 0; ks < 8; ++ks) {
            bq[na][ks][0] = Qs[nc][ks * 8 + tig];
            bq[na][ks][1] = Qs[nc][ks * 8 + tig + 4];
        }
    }
    float m1c[2][2];
#pragma unroll
    for (int na = 0; na < 2; ++na) {
        const int qc = q0 + wn1 * 16 + na * 8 + 2 * tig;
        m1c[na][0] = m1[bh * S_ + qc];
        m1c[na][1] = m1[bh * S_ + qc + 1];
    }

    float o[4][4];
#pragma unroll
    for (int na = 0; na < 4; ++na)
#pragma unroll
        for (int r = 0; r < 4; ++r) o[na][r] = 0.f;
    float zp[2][2] = {{0.f, 0.f}, {0.f, 0.f}};

    const int klo  = (q0 >= 128) ? q0 - 128 : 0;
    const int kend = (q0 + 192 < S_) ? q0 + 192 : S_;

    for (int kt = klo; kt < kend; kt += 32) {
        __syncthreads();
        {
            const int r  = tid >> 3;
            const int c0 = (tid & 7) * 8;
            const float* kp = K + rowbase + (kt + r) * C_ + c0;
            const float* vp = V + rowbase + (kt + r) * C_ + c0;
#pragma unroll
            for (int j = 0; j < 2; ++j) {
                float4 a = *(const float4*)(kp + j * 4);
                float4 c = *(const float4*)(vp + j * 4);
                uint4 ta, tc;
                ta.x = f2tf(a.x); ta.y = f2tf(a.y); ta.z = f2tf(a.z); ta.w = f2tf(a.w);
                tc.x = f2tf(c.x); tc.y = f2tf(c.y); tc.z = f2tf(c.z); tc.w = f2tf(c.w);
                *(uint4*)&Ks[r][c0 + j * 4] = ta;
                *(uint4*)&Vs[r][c0 + j * 4] = tc;
            }
        }
        __syncthreads();

        float s[2][4];
#pragma unroll
        for (int na = 0; na < 2; ++na)
#pragma unroll
            for (int r = 0; r < 4; ++r) s[na][r] = 0.f;

        const int mr1 = wm1 * 16;
#pragma unroll
        for (int ks = 0; ks < 8; ++ks) {
            const int k0 = ks * 8;
            unsigned a[4];
            a[0] = Ks[mr1 + g][k0 + tig];
            a[1] = Ks[mr1 + g + 8][k0 + tig];
            a[2] = Ks[mr1 + g][k0 + tig + 4];
            a[3] = Ks[mr1 + g + 8][k0 + tig + 4];
            MMA_TF32(s[0], a, bq[0][ks]);
            MMA_TF32(s[1], a, bq[1][ks]);
        }

#pragma unroll
        for (int na = 0; na < 2; ++na) {
            const int colq = wn1 * 16 + na * 8 + 2 * tig;
#pragma unroll
            for (int r2 = 0; r2 < 2; ++r2) {
                const int keyrow = wm1 * 16 + g + r2 * 8;
                const int key = kt + keyrow;
#pragma unroll
                for (int j = 0; j < 2; ++j) {
                    const float sv = s[na][r2 * 2 + j];
                    const int d = key - (q0 + colq + j);
                    float t = __expf(sv * 0.125f - m1c[na][j]);
                    float w = __expf(t) - 1.0f;
                    if (d < -128 || d > 127) w = 0.f;
                    const unsigned wt = f2tf(w);
                    zp[na][j] += __uint_as_float(wt);
                    Ws[keyrow][colq + j] = wt;
                }
            }
        }
        __syncthreads();

        const int mr2 = wm2 * 16;
#pragma unroll
        for (int ks = 0; ks < 4; ++ks) {
            const int k0 = ks * 8;
            unsigned a[4];
            a[0] = Ws[k0 + tig][mr2 + g];
            a[1] = Ws[k0 + tig][mr2 + g + 8];
            a[2] = Ws[k0 + tig + 4][mr2 + g];
            a[3] = Ws[k0 + tig + 4][mr2 + g + 8];
#pragma unroll
            for (int na = 0; na < 4; ++na) {
                unsigned bb[2];
                const int nc = wn2 * 32 + na * 8 + g;
                bb[0] = Vs[k0 + tig][nc];
                bb[1] = Vs[k0 + tig + 4][nc];
                MMA_TF32(o[na], a, bb);
            }
        }
    }

#pragma unroll
    for (int off = 4; off <= 16; off <<= 1)
#pragma unroll
        for (int na = 0; na < 2; ++na) {
            zp[na][0] += __shfl_xor_sync(0xffffffffu, zp[na][0], off);
            zp[na][1] += __shfl_xor_sync(0xffffffffu, zp[na][1], off);
        }
    if (g == 0) {
#pragma unroll
        for (int na = 0; na < 2; ++na) {
            zred[wm1][wn1 * 16 + na * 8 + 2 * tig + 0] = zp[na][0];
            zred[wm1][wn1 * 16 + na * 8 + 2 * tig + 1] = zp[na][1];
        }
    }
    __syncthreads();

    const float* vsp = vs + bh * 64;
#pragma unroll
    for (int r2 = 0; r2 < 2; ++r2) {
        const int row = wm2 * 16 + g + r2 * 8;
        const float inv = 1.0f / ((float)S_ + zred[0][row] + zred[1][row]);
        float* op = O + rowbase + (q0 + row) * C_;
#pragma unroll
        for (int na = 0; na < 4; ++na) {
            const int col = wn2 * 32 + na * 8 + 2 * tig;
            float2 ov;
            ov.x = (o[na][r2 * 2 + 0] + vsp[col])     * inv;
            ov.y = (o[na][r2 * 2 + 1] + vsp[col + 1]) * inv;
            *(float2*)(op + col) = ov;
        }
    }
}

// ============================================================================
extern "C" void kernel_launch(void* const* d_in, const int* in_sizes, int n_in,
                              void* d_out, int out_size)
{
    (void)in_sizes; (void)n_in; (void)out_size;
    const float* x  = (const float*)d_in[0];
    const float* Wq = (const float*)d_in[1];
    const float* Wk = (const float*)d_in[2];
    const float* Wv = (const float*)d_in[3];
    const float* Wo = (const float*)d_in[4];
    float* out = (float*)d_out;

    float *Qp, *Kp, *Vp, *Ap, *m1p, *vsp;
    cudaGetSymbolAddress((void**)&Qp,  g_Q);
    cudaGetSymbolAddress((void**)&Kp,  g_K);
    cudaGetSymbolAddress((void**)&Vp,  g_V);
    cudaGetSymbolAddress((void**)&Ap,  g_A);
    cudaGetSymbolAddress((void**)&m1p, g_m1);
    cudaGetSymbolAddress((void**)&vsp, g_vs);

    // allow >48KB dynamic smem (idempotent; not an allocation / stream op)
    cudaFuncSetAttribute(tgemm_qkv_db,
                         cudaFuncAttributeMaxDynamicSharedMemorySize,
                         GEMM_SMEM_BYTES);
    cudaFuncSetAttribute(tgemm_db,
                         cudaFuncAttributeMaxDynamicSharedMemorySize,
                         GEMM_SMEM_BYTES);

    dim3 gq(C_ / 128, M_ / 128, 3);         // (8, 32, 3)
    tgemm_qkv_db<<<gq, 256, GEMM_SMEM_BYTES>>>(x, Wq, Wk, Wv, Qp, Kp, Vp);

    score_max_t<<<dim3(S_ / 64, B_ * H_), 256>>>(Qp, Kp, m1p);
    vsum_k<<<B_ * H_, 256>>>(Vp, vsp);
    band_attn_t<<<dim3(S_ / 64, B_ * H_), 256>>>(Qp, Kp, Vp, m1p, vsp, Ap);

    dim3 gg(C_ / 128, M_ / 128);            // (8, 32)
    tgemm_db<<<gg, 256, GEMM_SMEM_BYTES>>>(Ap, Wo, out, C_, C_);
}

// round 9
// speedup vs baseline: 1.9429x; 1.1689x over previous
#include <cuda_runtime.h>
#include <math.h>
#include <cstdint>

#define B_   2
#define S_   2048
#define C_   1024
#define H_   16
#define DH_  64
#define M_   (B_ * S_)       // 4096 rows

// ---- scratch (device globals; no allocation allowed) ----
__device__ float g_Q[M_ * C_];
__device__ float g_K[M_ * C_];
__device__ float g_V[M_ * C_];
__device__ float g_A[M_ * C_];           // attention output (tf32-rounded)
__device__ float g_X[M_ * C_];           // tf32-rounded x
__device__ float g_Wt[4 * C_ * C_];      // tf32-rounded weights (natural [K][N])
__device__ float g_m1[B_ * H_ * S_];     // full-row max of scores (already /8)
__device__ float g_vs[B_ * H_ * DH_];    // sum over all keys of V per (b,h)

__device__ __forceinline__ unsigned f2tf(float x) {
    unsigned r;
    asm("cvt.rna.tf32.f32 %0, %1;" : "=r"(r) : "f"(x));
    return r;
}

__device__ __forceinline__ uint32_t s2u(const void* p) {
    uint32_t a;
    asm("{ .reg .u64 t; cvta.to.shared.u64 t, %1; cvt.u32.u64 %0, t; }"
        : "=r"(a) : "l"(p));
    return a;
}

__device__ __forceinline__ void cp16(uint32_t d, const void* s) {
    asm volatile("cp.async.cg.shared.global [%0], [%1], 16;" :: "r"(d), "l"(s));
}
#define CP_COMMIT() asm volatile("cp.async.commit_group;" ::: "memory")
#define CP_WAIT2()  asm volatile("cp.async.wait_group 2;" ::: "memory")

#define MMA_TF32(c, a, b)                                                     \
    asm volatile(                                                             \
        "mma.sync.aligned.m16n8k8.row.col.f32.tf32.tf32.f32 "                 \
        "{%0,%1,%2,%3},{%4,%5,%6,%7},{%8,%9},{%0,%1,%2,%3};"                  \
        : "+f"((c)[0]), "+f"((c)[1]), "+f"((c)[2]), "+f"((c)[3])              \
        : "r"((a)[0]), "r"((a)[1]), "r"((a)[2]), "r"((a)[3]),                 \
          "r"((b)[0]), "r"((b)[1]))

// ============================================================================
// tf32 rounding kernel (float4 grid-stride-free; exact sizes)
// ============================================================================
__global__ __launch_bounds__(256) void round_tf32(
    const float* __restrict__ src, float* __restrict__ dst)
{
    const int i = blockIdx.x * 256 + threadIdx.x;
    float4 v = ((const float4*)src)[i];
    uint4 t;
    t.x = f2tf(v.x); t.y = f2tf(v.y); t.z = f2tf(v.z); t.w = f2tf(v.w);
    ((uint4*)dst)[i] = t;
}

// ============================================================================
// cp.async 3-stage tf32 GEMM: C = A[M,K] @ B[K,N], inputs pre-rounded to
// tf32 values. 128x128x32 tile, 8 warps (4x2), warp tile 32x64.
// smem: As[3][128][36] + Bs[3][32][128] = 104448 B dynamic.
// ============================================================================
#define AS_WORDS (128 * 36)
#define BS_WORDS (32 * 128)
#define GEMM_SMEM_BYTES (3 * (AS_WORDS + BS_WORDS) * 4)

__device__ __forceinline__ void issue_tile(
    const float* __restrict__ A, const float* __restrict__ B,
    int K, int N, int bm, int bn, int kb,
    uint32_t sbase, int stage, int tid)
{
#pragma unroll
    for (int u = 0; u < 4; ++u) {
        const int f = tid + 256 * u;
        const int row = f >> 3;
        const int k4 = (f & 7) * 4;
        cp16(sbase + (uint32_t)(stage * AS_WORDS + row * 36 + k4) * 4,
             A + (size_t)(bm + row) * K + kb + k4);
    }
    const int bk = tid >> 3;
    const int n0 = (tid & 7) * 16;
    const unsigned sw = (bk & 3) << 3;
#pragma unroll
    for (int j = 0; j < 4; ++j) {
        cp16(sbase + (uint32_t)(3 * AS_WORDS + stage * BS_WORDS + bk * 128 +
                                ((n0 + j * 4) ^ sw)) * 4,
             B + (size_t)(kb + bk) * N + bn + n0 + j * 4);
    }
}

__device__ __forceinline__ void gemm_ca_body(
    const float* __restrict__ A, const float* __restrict__ B,
    float* __restrict__ C, int N, int K)
{
    extern __shared__ unsigned smbuf[];
    const uint32_t sbase = s2u(smbuf);

    const int tid = threadIdx.x;
    const int bm = blockIdx.y * 128;
    const int bn = blockIdx.x * 128;

    const int wid  = tid >> 5;
    const int lane = tid & 31;
    const int g    = lane >> 2;
    const int tig  = lane & 3;
    const int warpM = wid >> 1;
    const int warpN = wid & 1;
    const unsigned swz = tig << 3;

    float c[2][8][4];
#pragma unroll
    for (int i = 0; i < 2; ++i)
#pragma unroll
        for (int j = 0; j < 8; ++j)
#pragma unroll
            for (int r = 0; r < 4; ++r) c[i][j][r] = 0.f;

    const int nt = K >> 5;

    issue_tile(A, B, K, N, bm, bn, 0,  sbase, 0, tid); CP_COMMIT();
    issue_tile(A, B, K, N, bm, bn, 32, sbase, 1, tid); CP_COMMIT();

    for (int t = 0; t < nt; ++t) {
        if (t + 2 < nt)
            issue_tile(A, B, K, N, bm, bn, (t + 2) * 32, sbase, (t + 2) % 3, tid);
        CP_COMMIT();           // uniform group count (empty groups at tail)
        CP_WAIT2();            // tile t resident
        __syncthreads();

        const unsigned* Ab = smbuf + (t % 3) * AS_WORDS;
        const unsigned* Bb = smbuf + 3 * AS_WORDS + (t % 3) * BS_WORDS;

#pragma unroll
        for (int ks = 0; ks < 4; ++ks) {
            const int k0 = ks * 8;
            unsigned a[2][4];
#pragma unroll
            for (int m2 = 0; m2 < 2; ++m2) {
                const int mr = warpM * 32 + m2 * 16;
                a[m2][0] = Ab[(mr + g) * 36 + k0 + tig];
                a[m2][1] = Ab[(mr + g + 8) * 36 + k0 + tig];
                a[m2][2] = Ab[(mr + g) * 36 + k0 + tig + 4];
                a[m2][3] = Ab[(mr + g + 8) * 36 + k0 + tig + 4];
            }
#pragma unroll
            for (int j = 0; j < 8; ++j) {
                unsigned b[2];
                const unsigned nc = (unsigned)(warpN * 64 + j * 8 + g) ^ swz;
                b[0] = Bb[(k0 + tig) * 128 + nc];
                b[1] = Bb[(k0 + tig + 4) * 128 + nc];
                MMA_TF32(c[0][j], a[0], b);
                MMA_TF32(c[1][j], a[1], b);
            }
        }
        __syncthreads();       // compute done before next issue overwrites buf
    }

#pragma unroll
    for (int m2 = 0; m2 < 2; ++m2) {
#pragma unroll
        for (int j = 0; j < 8; ++j) {
            const int row = bm + warpM * 32 + m2 * 16 + g;
            const int col = bn + warpN * 64 + j * 8 + 2 * tig;
            *(float2*)&C[(size_t)row * N + col]       = make_float2(c[m2][j][0], c[m2][j][1]);
            *(float2*)&C[(size_t)(row + 8) * N + col] = make_float2(c[m2][j][2], c[m2][j][3]);
        }
    }
}

__global__ __launch_bounds__(256, 2) void tgemm_ca(
    const float* __restrict__ A, const float* __restrict__ B,
    float* __restrict__ C, int N, int K)
{
    gemm_ca_body(A, B, C, N, K);
}

__global__ __launch_bounds__(256, 2) void tgemm_ca_qkv(
    const float* __restrict__ A, const float* __restrict__ W,
    float* __restrict__ C0, float* __restrict__ C1, float* __restrict__ C2)
{
    const int z = blockIdx.z;
    float* C = (z == 0) ? C0 : (z == 1) ? C1 : C2;
    gemm_ca_body(A, W + (size_t)z * C_ * C_, C, C_, C_);
}

// ============================================================================
// tf32 score row-max (unchanged R3/R7 winner)
// ============================================================================
__global__ __launch_bounds__(256, 2) void score_max_t(
    const float* __restrict__ Q, const float* __restrict__ K,
    float* __restrict__ m1)
{
    __shared__ unsigned Ks[2][64][68];
    __shared__ float buf[4][64];

    const int bh = blockIdx.y;
    const int b = bh >> 4, h = bh & 15;
    const int q0 = blockIdx.x * 64;
    const int tid = threadIdx.x;
    const int rowbase = (b * S_) * C_ + h * DH_;

    const int wid  = tid >> 5;
    const int lane = tid & 31;
    const int g    = lane >> 2;
    const int tig  = lane & 3;
    const int warpM = wid & 3;
    const int warpN = wid >> 2;

    const int ld_r = tid >> 2;
    const int ld_c = (tid & 3) * 4;

    {
        const float* qp = Q + rowbase + (q0 + ld_r) * C_ + ld_c;
#pragma unroll
        for (int j = 0; j < 4; ++j) {
            float4 v = *(const float4*)(qp + j * 16);
            Ks[0][ld_r][ld_c + j * 16 + 0] = f2tf(v.x);
            Ks[0][ld_r][ld_c + j * 16 + 1] = f2tf(v.y);
            Ks[0][ld_r][ld_c + j * 16 + 2] = f2tf(v.z);
            Ks[0][ld_r][ld_c + j * 16 + 3] = f2tf(v.w);
        }
    }
    __syncthreads();

    unsigned bq[4][8][2];
#pragma unroll
    for (int na = 0; na < 4; ++na) {
        const int nc = warpN * 32 + na * 8 + g;
#pragma unroll
        for (int ks = 0; ks < 8; ++ks) {
            bq[na][ks][0] = Ks[0][nc][ks * 8 + tig];
            bq[na][ks][1] = Ks[0][nc][ks * 8 + tig + 4];
        }
    }
    __syncthreads();

    float rmax[4][2];
#pragma unroll
    for (int na = 0; na < 4; ++na) { rmax[na][0] = -1e30f; rmax[na][1] = -1e30f; }

    float4 kv[4];
    {
        const float* kp = K + rowbase + ld_r * C_ + ld_c;
#pragma unroll
        for (int j = 0; j < 4; ++j) kv[j] = *(const float4*)(kp + j * 16);
    }

    for (int t = 0; t < S_ / 64; ++t) {
        const int cur = t & 1;
#pragma unroll
        for (int j = 0; j < 4; ++j) {
            Ks[cur][ld_r][ld_c + j * 16 + 0] = f2tf(kv[j].x);
            Ks[cur][ld_r][ld_c + j * 16 + 1] = f2tf(kv[j].y);
            Ks[cur][ld_r][ld_c + j * 16 + 2] = f2tf(kv[j].z);
            Ks[cur][ld_r][ld_c + j * 16 + 3] = f2tf(kv[j].w);
        }
        __syncthreads();

        if (t + 1 < S_ / 64) {
            const float* kp = K + rowbase + ((t + 1) * 64 + ld_r) * C_ + ld_c;
#pragma unroll
            for (int j = 0; j < 4; ++j) kv[j] = *(const float4*)(kp + j * 16);
        }

        float c[4][4];
#pragma unroll
        for (int na = 0; na < 4; ++na)
#pragma unroll
            for (int r = 0; r < 4; ++r) c[na][r] = 0.f;

        const int mr = warpM * 16;
#pragma unroll
        for (int ks = 0; ks < 8; ++ks) {
            const int k0 = ks * 8;
            unsigned a[4];
            a[0] = Ks[cur][mr + g][k0 + tig];
            a[1] = Ks[cur][mr + g + 8][k0 + tig];
            a[2] = Ks[cur][mr + g][k0 + tig + 4];
            a[3] = Ks[cur][mr + g + 8][k0 + tig + 4];
#pragma unroll
            for (int na = 0; na < 4; ++na)
                MMA_TF32(c[na], a, bq[na][ks]);
        }

#pragma unroll
        for (int na = 0; na < 4; ++na) {
            rmax[na][0] = fmaxf(rmax[na][0], fmaxf(c[na][0], c[na][2]));
            rmax[na][1] = fmaxf(rmax[na][1], fmaxf(c[na][1], c[na][3]));
        }
    }

#pragma unroll
    for (int off = 4; off <= 16; off <<= 1)
#pragma unroll
        for (int na = 0; na < 4; ++na) {
            rmax[na][0] = fmaxf(rmax[na][0], __shfl_xor_sync(0xffffffffu, rmax[na][0], off));
            rmax[na][1] = fmaxf(rmax[na][1], __shfl_xor_sync(0xffffffffu, rmax[na][1], off));
        }

    if (g == 0) {
#pragma unroll
        for (int na = 0; na < 4; ++na) {
            buf[warpM][warpN * 32 + na * 8 + tig * 2 + 0] = rmax[na][0];
            buf[warpM][warpN * 32 + na * 8 + tig * 2 + 1] = rmax[na][1];
        }
    }
    __syncthreads();
    if (tid < 64) {
        float m = fmaxf(fmaxf(buf[0][tid], buf[1][tid]),
                        fmaxf(buf[2][tid], buf[3][tid]));
        m1[bh * S_ + q0 + tid] = m * 0.125f;
    }
}

// ============================================================================
// V column sums per (b,h)
// ============================================================================
__global__ __launch_bounds__(256) void vsum_k(
    const float* __restrict__ V, float* __restrict__ vs)
{
    __shared__ float red[4][64];
    const int bh = blockIdx.x;
    const int b = bh >> 4, h = bh & 15;
    const int tid = threadIdx.x;
    const int d = tid & 63, g = tid >> 6;
    const float* p = V + (b * S_) * C_ + h * DH_ + d;
    float s = 0.f;
    for (int k = g; k < S_; k += 4) s += p[k * C_];
    red[g][d] = s;
    __syncthreads();
    if (tid < 64)
        vs[bh * 64 + tid] = red[0][tid] + red[1][tid] + red[2][tid] + red[3][tid];
}

// ============================================================================
// Tensor-core banded attention (R6 winner; output now tf32-rounded so the
// out-projection can consume it without converting).
// ============================================================================
__global__ __launch_bounds__(256) void band_attn_t(
    const float* __restrict__ Q, const float* __restrict__ K,
    const float* __restrict__ V, const float* __restrict__ m1,
    const float* __restrict__ vs, float* __restrict__ O)
{
    __shared__ unsigned Qs[64][68];
    __shared__ unsigned Ks[32][76];
    __shared__ unsigned Vs[32][76];
    __shared__ unsigned Ws[32][76];
    __shared__ float zred[2][64];

    const int bh = blockIdx.y;
    const int b = bh >> 4, h = bh & 15;
    const int q0 = blockIdx.x * 64;
    const int tid = threadIdx.x;
    const int rowbase = (b * S_) * C_ + h * DH_;

    const int wid  = tid >> 5;
    const int lane = tid & 31;
    const int g    = lane >> 2;
    const int tig  = lane & 3;
    const int wm1 = wid & 1;
    const int wn1 = wid >> 1;
    const int wm2 = wid >> 1;
    const int wn2 = wid & 1;

    {
        const int r  = tid >> 2;
        const int c0 = (tid & 3) * 16;
        const float* qp = Q + rowbase + (q0 + r) * C_ + c0;
#pragma unroll
        for (int j = 0; j < 4; ++j) {
            float4 v = *(const float4*)(qp + j * 4);
            uint4 t;
            t.x = f2tf(v.x); t.y = f2tf(v.y); t.z = f2tf(v.z); t.w = f2tf(v.w);
            *(uint4*)&Qs[r][c0 + j * 4] = t;
        }
    }
    __syncthreads();

    unsigned bq[2][8][2];
#pragma unroll
    for (int na = 0; na < 2; ++na) {
        const int nc = wn1 * 16 + na * 8 + g;
#pragma unroll
        for (int ks = 0; ks < 8; ++ks) {
            bq[na][ks][0] = Qs[nc][ks * 8 + tig];
            bq[na][ks][1] = Qs[nc][ks * 8 + tig + 4];
        }
    }
    float m1c[2][2];
#pragma unroll
    for (int na = 0; na < 2; ++na) {
        const int qc = q0 + wn1 * 16 + na * 8 + 2 * tig;
        m1c[na][0] = m1[bh * S_ + qc];
        m1c[na][1] = m1[bh * S_ + qc + 1];
    }

    float o[4][4];
#pragma unroll
    for (int na = 0; na < 4; ++na)
#pragma unroll
        for (int r = 0; r < 4; ++r) o[na][r] = 0.f;
    float zp[2][2] = {{0.f, 0.f}, {0.f, 0.f}};

    const int klo  = (q0 >= 128) ? q0 - 128 : 0;
    const int kend = (q0 + 192 < S_) ? q0 + 192 : S_;

    for (int kt = klo; kt < kend; kt += 32) {
        __syncthreads();
        {
            const int r  = tid >> 3;
            const int c0 = (tid & 7) * 8;
            const float* kp = K + rowbase + (kt + r) * C_ + c0;
            const float* vp = V + rowbase + (kt + r) * C_ + c0;
#pragma unroll
            for (int j = 0; j < 2; ++j) {
                float4 a = *(const float4*)(kp + j * 4);
                float4 c = *(const float4*)(vp + j * 4);
                uint4 ta, tc;
                ta.x = f2tf(a.x); ta.y = f2tf(a.y); ta.z = f2tf(a.z); ta.w = f2tf(a.w);
                tc.x = f2tf(c.x); tc.y = f2tf(c.y); tc.z = f2tf(c.z); tc.w = f2tf(c.w);
                *(uint4*)&Ks[r][c0 + j * 4] = ta;
                *(uint4*)&Vs[r][c0 + j * 4] = tc;
            }
        }
        __syncthreads();

        float s[2][4];
#pragma unroll
        for (int na = 0; na < 2; ++na)
#pragma unroll
            for (int r = 0; r < 4; ++r) s[na][r] = 0.f;

        const int mr1 = wm1 * 16;
#pragma unroll
        for (int ks = 0; ks < 8; ++ks) {
            const int k0 = ks * 8;
            unsigned a[4];
            a[0] = Ks[mr1 + g][k0 + tig];
            a[1] = Ks[mr1 + g + 8][k0 + tig];
            a[2] = Ks[mr1 + g][k0 + tig + 4];
            a[3] = Ks[mr1 + g + 8][k0 + tig + 4];
            MMA_TF32(s[0], a, bq[0][ks]);
            MMA_TF32(s[1], a, bq[1][ks]);
        }

#pragma unroll
        for (int na = 0; na < 2; ++na) {
            const int colq = wn1 * 16 + na * 8 + 2 * tig;
#pragma unroll
            for (int r2 = 0; r2 < 2; ++r2) {
                const int keyrow = wm1 * 16 + g + r2 * 8;
                const int key = kt + keyrow;
#pragma unroll
                for (int j = 0; j < 2; ++j) {
                    const float sv = s[na][r2 * 2 + j];
                    const int d = key - (q0 + colq + j);
                    float t = __expf(sv * 0.125f - m1c[na][j]);
                    float w = __expf(t) - 1.0f;
                    if (d < -128 || d > 127) w = 0.f;
                    const unsigned wt = f2tf(w);
                    zp[na][j] += __uint_as_float(wt);
                    Ws[keyrow][colq + j] = wt;
                }
            }
        }
        __syncthreads();

        const int mr2 = wm2 * 16;
#pragma unroll
        for (int ks = 0; ks < 4; ++ks) {
            const int k0 = ks * 8;
            unsigned a[4];
            a[0] = Ws[k0 + tig][mr2 + g];
            a[1] = Ws[k0 + tig][mr2 + g + 8];
            a[2] = Ws[k0 + tig + 4][mr2 + g];
            a[3] = Ws[k0 + tig + 4][mr2 + g + 8];
#pragma unroll
            for (int na = 0; na < 4; ++na) {
                unsigned bb[2];
                const int nc = wn2 * 32 + na * 8 + g;
                bb[0] = Vs[k0 + tig][nc];
                bb[1] = Vs[k0 + tig + 4][nc];
                MMA_TF32(o[na], a, bb);
            }
        }
    }

#pragma unroll
    for (int off = 4; off <= 16; off <<= 1)
#pragma unroll
        for (int na = 0; na < 2; ++na) {
            zp[na][0] += __shfl_xor_sync(0xffffffffu, zp[na][0], off);
            zp[na][1] += __shfl_xor_sync(0xffffffffu, zp[na][1], off);
        }
    if (g == 0) {
#pragma unroll
        for (int na = 0; na < 2; ++na) {
            zred[wm1][wn1 * 16 + na * 8 + 2 * tig + 0] = zp[na][0];
            zred[wm1][wn1 * 16 + na * 8 + 2 * tig + 1] = zp[na][1];
        }
    }
    __syncthreads();

    const float* vsp = vs + bh * 64;
#pragma unroll
    for (int r2 = 0; r2 < 2; ++r2) {
        const int row = wm2 * 16 + g + r2 * 8;
        const float inv = 1.0f / ((float)S_ + zred[0][row] + zred[1][row]);
        float* op = O + rowbase + (q0 + row) * C_;
#pragma unroll
        for (int na = 0; na < 4; ++na) {
            const int col = wn2 * 32 + na * 8 + 2 * tig;
            float2 ov;
            ov.x = __uint_as_float(f2tf((o[na][r2 * 2 + 0] + vsp[col])     * inv));
            ov.y = __uint_as_float(f2tf((o[na][r2 * 2 + 1] + vsp[col + 1]) * inv));
            *(float2*)(op + col) = ov;
        }
    }
}

// ============================================================================
extern "C" void kernel_launch(void* const* d_in, const int* in_sizes, int n_in,
                              void* d_out, int out_size)
{
    (void)in_sizes; (void)n_in; (void)out_size;
    const float* x  = (const float*)d_in[0];
    const float* Wq = (const float*)d_in[1];
    const float* Wk = (const float*)d_in[2];
    const float* Wv = (const float*)d_in[3];
    const float* Wo = (const float*)d_in[4];
    float* out = (float*)d_out;

    float *Qp, *Kp, *Vp, *Ap, *Xp, *Wtp, *m1p, *vsp;
    cudaGetSymbolAddress((void**)&Qp,  g_Q);
    cudaGetSymbolAddress((void**)&Kp,  g_K);
    cudaGetSymbolAddress((void**)&Vp,  g_V);
    cudaGetSymbolAddress((void**)&Ap,  g_A);
    cudaGetSymbolAddress((void**)&Xp,  g_X);
    cudaGetSymbolAddress((void**)&Wtp, g_Wt);
    cudaGetSymbolAddress((void**)&m1p, g_m1);
    cudaGetSymbolAddress((void**)&vsp, g_vs);

    cudaFuncSetAttribute(tgemm_ca,
                         cudaFuncAttributeMaxDynamicSharedMemorySize,
                         GEMM_SMEM_BYTES);
    cudaFuncSetAttribute(tgemm_ca_qkv,
                         cudaFuncAttributeMaxDynamicSharedMemorySize,
                         GEMM_SMEM_BYTES);

    // tf32-round all GEMM inputs once (numerics identical to in-GEMM cvt)
    round_tf32<<<(M_ * C_) / 1024, 256>>>(x, Xp);
    round_tf32<<<(C_ * C_) / 1024, 256>>>(Wq, Wtp + 0 * C_ * C_);
    round_tf32<<<(C_ * C_) / 1024, 256>>>(Wk, Wtp + 1 * C_ * C_);
    round_tf32<<<(C_ * C_) / 1024, 256>>>(Wv, Wtp + 2 * C_ * C_);
    round_tf32<<<(C_ * C_) / 1024, 256>>>(Wo, Wtp + 3 * C_ * C_);

    dim3 gq(C_ / 128, M_ / 128, 3);         // (8, 32, 3)
    tgemm_ca_qkv<<<gq, 256, GEMM_SMEM_BYTES>>>(Xp, Wtp, Qp, Kp, Vp);

    score_max_t<<<dim3(S_ / 64, B_ * H_), 256>>>(Qp, Kp, m1p);
    vsum_k<<<B_ * H_, 256>>>(Vp, vsp);
    band_attn_t<<<dim3(S_ / 64, B_ * H_), 256>>>(Qp, Kp, Vp, m1p, vsp, Ap);

    dim3 gg(C_ / 128, M_ / 128);            // (8, 32)
    tgemm_ca<<<gg, 256, GEMM_SMEM_BYTES>>>(Ap, Wtp + 3 * C_ * C_, out, C_, C_);
}